// round 2
// baseline (speedup 1.0000x reference)
#include <cuda_runtime.h>
#include <cooperative_groups.h>
#include <cstdint>

namespace cg = cooperative_groups;

#define BATCH    8
#define NPTS     65536
#define NSAMP    1024
#define NTHREADS 512
#define NWARPS   (NTHREADS / 32)

struct __align__(8) CSlot { unsigned long long key; float x, y, z; };

__device__ __forceinline__ unsigned long long pk2(float lo, float hi) {
    unsigned long long r; asm("mov.b64 %0,{%1,%2};" : "=l"(r) : "f"(lo), "f"(hi)); return r;
}
__device__ __forceinline__ void up2(unsigned long long v, float& lo, float& hi) {
    asm("mov.b64 {%0,%1},%2;" : "=f"(lo), "=f"(hi) : "l"(v));
}
__device__ __forceinline__ unsigned long long add2(unsigned long long a, unsigned long long b) {
    unsigned long long r; asm("add.rn.f32x2 %0,%1,%2;" : "=l"(r) : "l"(a), "l"(b)); return r;
}
__device__ __forceinline__ unsigned long long mul2(unsigned long long a, unsigned long long b) {
    unsigned long long r; asm("mul.rn.f32x2 %0,%1,%2;" : "=l"(r) : "l"(a), "l"(b)); return r;
}

extern __shared__ float dynsmem[];

template<int CS>
__global__ void __launch_bounds__(NTHREADS, 1)
fps_kernel(const float* __restrict__ input, float* __restrict__ out)
{
    constexpr int NPC   = NPTS / CS;        // points per CTA
    constexpr int PPT   = NPC / NTHREADS;   // points per thread
    constexpr int PAIRS = PPT / 2;

    cg::cluster_group cluster = cg::this_cluster();
    const unsigned rank = cluster.block_rank();
    const int b    = blockIdx.x / CS;
    const int tid  = threadIdx.x;
    const int lane = tid & 31;
    const int warp = tid >> 5;

    // SMEM SoA copy of this CTA's points (winner-coordinate lookup only)
    float* xs = dynsmem;
    float* ys = xs + NPC;
    float* zs = ys + NPC;

    __shared__ unsigned long long wkey[NWARPS];
    __shared__ CSlot cslots[2][CS];          // double-buffered cross-CTA exchange

    const float* pb = input + (size_t)b * NPTS * 3;
    const unsigned g0 = rank * NPC + (unsigned)tid * PPT;

    // ---- one-time load: PPT points into registers (f32x2-packed) + SMEM SoA ----
    float f[PPT * 3];
    const float4* src4 = (const float4*)(pb + (size_t)g0 * 3);
    #pragma unroll
    for (int i = 0; i < (PPT * 3) / 4; i++) {
        float4 v = src4[i];
        f[4*i] = v.x; f[4*i+1] = v.y; f[4*i+2] = v.z; f[4*i+3] = v.w;
    }
    unsigned long long px[PAIRS], py[PAIRS], pz[PAIRS];
    #pragma unroll
    for (int j = 0; j < PAIRS; j++) {
        px[j] = pk2(f[6*j+0], f[6*j+3]);
        py[j] = pk2(f[6*j+1], f[6*j+4]);
        pz[j] = pk2(f[6*j+2], f[6*j+5]);
    }
    {
        const unsigned l0 = (unsigned)tid * PPT;
        #pragma unroll
        for (int i = 0; i < PPT; i++) {
            xs[l0 + i] = f[3*i]; ys[l0 + i] = f[3*i+1]; zs[l0 + i] = f[3*i+2];
        }
    }

    float md[PPT];
    #pragma unroll
    for (int i = 0; i < PPT; i++) md[i] = 1e10f;   // BIG, matches reference

    // first selection is index 0 (PointNet++ convention)
    float cx = pb[0], cy = pb[1], cz = pb[2];
    if (rank == 0 && tid == 0) {
        out[(size_t)b * NSAMP] = 0.0f;
        float* os = out + BATCH * NSAMP + (size_t)b * NSAMP * 3;
        os[0] = cx; os[1] = cy; os[2] = cz;
    }

    for (int k = 1; k < NSAMP; k++) {
        // ---- distance update (non-contracted mul/add — matches reference rounding) ----
        const unsigned long long ncx = pk2(-cx, -cx), ncy = pk2(-cy, -cy), ncz = pk2(-cz, -cz);
        #pragma unroll
        for (int j = 0; j < PAIRS; j++) {
            unsigned long long dx = add2(px[j], ncx);
            unsigned long long dy = add2(py[j], ncy);
            unsigned long long dz = add2(pz[j], ncz);
            unsigned long long s  = add2(add2(mul2(dx, dx), mul2(dy, dy)), mul2(dz, dz));
            float lo, hi; up2(s, lo, hi);
            md[2*j]   = fminf(md[2*j],   lo);
            md[2*j+1] = fminf(md[2*j+1], hi);
        }

        // ---- thread-local argmax: depth-log2(PPT) tournament, strict > keeps first index ----
        float v[PPT]; int id[PPT];
        #pragma unroll
        for (int i = 0; i < PPT; i++) { v[i] = md[i]; id[i] = i; }
        #pragma unroll
        for (int s = 1; s < PPT; s <<= 1) {
            #pragma unroll
            for (int i = 0; i < PPT; i += 2 * s)
                if (v[i + s] > v[i]) { v[i] = v[i + s]; id[i] = id[i + s]; }
        }
        const unsigned gidx = g0 + (unsigned)id[0];
        const unsigned db   = __float_as_uint(v[0]);   // dist >= 0 -> uint order == float order

        // ---- warp argmax: redux + ballot; lowest tied lane == smallest index ----
        unsigned wmax = __reduce_max_sync(0xFFFFFFFFu, db);
        unsigned ball = __ballot_sync(0xFFFFFFFFu, db == wmax);
        int srcl = __ffs(ball) - 1;
        unsigned wi = __shfl_sync(0xFFFFFFFFu, gidx, srcl);
        if (lane == 0)
            wkey[warp] = ((unsigned long long)wmax << 32)
                       | (unsigned long long)(0xFFFFFFFFu - wi);
        __syncthreads();

        const int p = k & 1;
        // ---- CTA argmax (warp 0) + parallel push: lane r pushes to cluster rank r ----
        if (warp == 0) {
            unsigned long long k64 = (lane < NWARPS) ? wkey[lane] : 0ULL;
            unsigned hi32 = (unsigned)(k64 >> 32);
            unsigned m  = __reduce_max_sync(0xFFFFFFFFu, hi32);
            unsigned bl = __ballot_sync(0xFFFFFFFFu, hi32 == m);
            int s2 = __ffs(bl) - 1;                       // lowest warp == smallest index
            unsigned long long ck = __shfl_sync(0xFFFFFFFFu, k64, s2);
            unsigned gi = 0xFFFFFFFFu - (unsigned)(ck & 0xFFFFFFFFull);
            unsigned li = gi - rank * NPC;                // CTA winner is always local
            float sx = xs[li], sy = ys[li], sz = zs[li];  // broadcast LDS, conflict-free
            if (lane < CS) {
                CSlot* rp = cluster.map_shared_rank(&cslots[p][rank], lane);
                rp->key = ck; rp->x = sx; rp->y = sy; rp->z = sz;
            }
        }
        cluster.sync();   // orders DSMEM stores, releases slots cluster-wide

        // ---- every thread resolves the cluster winner (tournament over CS slots) ----
        unsigned long long kk[CS]; int sid[CS];
        #pragma unroll
        for (int r = 0; r < CS; r++) { kk[r] = cslots[p][r].key; sid[r] = r; }
        #pragma unroll
        for (int s = 1; s < CS; s <<= 1) {
            #pragma unroll
            for (int r = 0; r < CS; r += 2 * s)
                if (kk[r + s] > kk[r]) { kk[r] = kk[r + s]; sid[r] = sid[r + s]; }
        }
        cx = cslots[p][sid[0]].x; cy = cslots[p][sid[0]].y; cz = cslots[p][sid[0]].z;

        if (rank == 0 && tid == 0) {
            unsigned widx = 0xFFFFFFFFu - (unsigned)(kk[0] & 0xFFFFFFFFull);
            out[(size_t)b * NSAMP + k] = (float)widx;
            float* os = out + BATCH * NSAMP + ((size_t)b * NSAMP + k) * 3;
            os[0] = cx; os[1] = cy; os[2] = cz;
        }
    }
}

extern "C" void kernel_launch(void* const* d_in, const int* in_sizes, int n_in,
                              void* d_out, int out_size)
{
    const float* input = (const float*)d_in[0];
    float* out = (float*)d_out;

    const int smem16 = 3 * (NPTS / 16) * 4;   // 48 KB
    const int smem8  = 3 * (NPTS / 8)  * 4;   // 96 KB

    cudaFuncSetAttribute(fps_kernel<16>, cudaFuncAttributeNonPortableClusterSizeAllowed, 1);
    cudaFuncSetAttribute(fps_kernel<16>, cudaFuncAttributeMaxDynamicSharedMemorySize, smem16);
    cudaFuncSetAttribute(fps_kernel<8>,  cudaFuncAttributeMaxDynamicSharedMemorySize, smem8);

    cudaLaunchConfig_t cfg = {};
    cfg.blockDim = {NTHREADS, 1, 1};
    cfg.stream = 0;
    cudaLaunchAttribute attr[1];
    attr[0].id = cudaLaunchAttributeClusterDimension;

    // Prefer a 16-CTA cluster (non-portable on sm_103a); verify before launching.
    attr[0].val.clusterDim = {16, 1, 1};
    cfg.attrs = attr; cfg.numAttrs = 1;
    cfg.gridDim = {BATCH * 16, 1, 1};
    cfg.dynamicSmemBytes = smem16;

    int maxCluster = 0;
    cudaOccupancyMaxPotentialClusterSize(&maxCluster, fps_kernel<16>, &cfg);

    if (maxCluster >= 16) {
        cudaLaunchKernelEx(&cfg, fps_kernel<16>, input, out);
    } else {
        attr[0].val.clusterDim = {8, 1, 1};
        cfg.gridDim = {BATCH * 8, 1, 1};
        cfg.dynamicSmemBytes = smem8;
        cudaLaunchKernelEx(&cfg, fps_kernel<8>, input, out);
    }
}

// round 3
// speedup vs baseline: 3.1044x; 3.1044x over previous
#include <cuda_runtime.h>
#include <cooperative_groups.h>
#include <cstdint>

namespace cg = cooperative_groups;

#define BATCH    8
#define NPTS     65536
#define NSAMP    1024
#define CS       8
#define NPC      (NPTS / CS)        // 8192 points per CTA
#define NTHREADS 512
#define PPT      (NPC / NTHREADS)   // 16 points per thread
#define PAIRS    (PPT / 2)
#define NWARPS   (NTHREADS / 32)    // 16
#define SLOT_TX  (CS * 20)          // 8 slots * (8B key + 8B xy + 4B z)

__device__ __forceinline__ unsigned long long pk2(float lo, float hi) {
    unsigned long long r; asm("mov.b64 %0,{%1,%2};" : "=l"(r) : "f"(lo), "f"(hi)); return r;
}
__device__ __forceinline__ void up2(unsigned long long v, float& lo, float& hi) {
    asm("mov.b64 {%0,%1},%2;" : "=f"(lo), "=f"(hi) : "l"(v));
}
__device__ __forceinline__ unsigned long long add2(unsigned long long a, unsigned long long b) {
    unsigned long long r; asm("add.rn.f32x2 %0,%1,%2;" : "=l"(r) : "l"(a), "l"(b)); return r;
}
__device__ __forceinline__ unsigned long long mul2(unsigned long long a, unsigned long long b) {
    unsigned long long r; asm("mul.rn.f32x2 %0,%1,%2;" : "=l"(r) : "l"(a), "l"(b)); return r;
}
__device__ __forceinline__ unsigned smem_u32(const void* p) {
    return (unsigned)__cvta_generic_to_shared(p);
}
__device__ __forceinline__ void mbar_wait(unsigned mbar, unsigned parity) {
    asm volatile(
        "{\n\t.reg .pred P;\n\t"
        "WAIT_%=:\n\t"
        "mbarrier.try_wait.parity.acquire.cta.shared::cta.b64 P, [%0], %1, 0x989680;\n\t"
        "@P bra DONE_%=;\n\t"
        "bra WAIT_%=;\n\t"
        "DONE_%=:\n\t}"
        :: "r"(mbar), "r"(parity) : "memory");
}

extern __shared__ float dynsmem[];

__global__ void __cluster_dims__(CS, 1, 1) __launch_bounds__(NTHREADS, 1)
fps_kernel(const float* __restrict__ input, float* __restrict__ out)
{
    cg::cluster_group cluster = cg::this_cluster();
    const unsigned rank = cluster.block_rank();
    const int b    = blockIdx.x / CS;
    const int tid  = threadIdx.x;
    const int lane = tid & 31;
    const int warp = tid >> 5;

    // SMEM SoA copy of this CTA's points (winner-coordinate lookup only)
    float* xs = dynsmem;
    float* ys = xs + NPC;
    float* zs = ys + NPC;

    __shared__ unsigned long long wkey[NWARPS];
    // slot = [key:u64][xy:u64][z:u32 in low half of u64] -> 24B stride, 20B payload
    __shared__ __align__(8) unsigned long long cslots[2][CS][3];
    __shared__ __align__(8) unsigned long long mbar[2];

    const unsigned mb0 = smem_u32(&mbar[0]);
    const unsigned mb1 = smem_u32(&mbar[1]);
    const unsigned slots0 = smem_u32(&cslots[0][0][0]);

    const float* pb = input + (size_t)b * NPTS * 3;
    const unsigned g0 = rank * NPC + (unsigned)tid * PPT;

    // ---- one-time: mbarrier init (arrive count 1 = the expect_tx arrival) ----
    if (tid == 0) {
        asm volatile("mbarrier.init.shared::cta.b64 [%0], 1;" :: "r"(mb0) : "memory");
        asm volatile("mbarrier.init.shared::cta.b64 [%0], 1;" :: "r"(mb1) : "memory");
        // phase consumed at k=1 (buffer 1) must be expected before ANY push(k=1)
        asm volatile("mbarrier.arrive.expect_tx.shared::cta.b64 _, [%0], %1;"
                     :: "r"(mb1), "r"(SLOT_TX) : "memory");
    }

    // ---- one-time load: PPT points into registers (f32x2-packed) + SMEM SoA ----
    float f[PPT * 3];
    const float4* src4 = (const float4*)(pb + (size_t)g0 * 3);
    #pragma unroll
    for (int i = 0; i < (PPT * 3) / 4; i++) {
        float4 v = src4[i];
        f[4*i] = v.x; f[4*i+1] = v.y; f[4*i+2] = v.z; f[4*i+3] = v.w;
    }
    unsigned long long px[PAIRS], py[PAIRS], pz[PAIRS];
    #pragma unroll
    for (int j = 0; j < PAIRS; j++) {
        px[j] = pk2(f[6*j+0], f[6*j+3]);
        py[j] = pk2(f[6*j+1], f[6*j+4]);
        pz[j] = pk2(f[6*j+2], f[6*j+5]);
    }
    {
        const unsigned l0 = (unsigned)tid * PPT;
        #pragma unroll
        for (int i = 0; i < PPT; i++) {
            xs[l0 + i] = f[3*i]; ys[l0 + i] = f[3*i+1]; zs[l0 + i] = f[3*i+2];
        }
    }

    float md[PPT];
    #pragma unroll
    for (int i = 0; i < PPT; i++) md[i] = 1e10f;   // BIG, matches reference

    // first selection is index 0 (PointNet++ convention)
    float cx = pb[0], cy = pb[1], cz = pb[2];
    if (rank == 0 && tid == 0) {
        out[(size_t)b * NSAMP] = 0.0f;
        float* os = out + BATCH * NSAMP + (size_t)b * NSAMP * 3;
        os[0] = cx; os[1] = cy; os[2] = cz;
    }

    // all mbarrier inits + SoA tiles visible cluster-wide before any st.async
    cluster.sync();

    unsigned ph0 = 0, ph1 = 0;   // phase parity per buffer

    for (int k = 1; k < NSAMP; k++) {
        // ---- distance update (non-contracted mul/add — matches reference rounding) ----
        const unsigned long long ncx = pk2(-cx, -cx), ncy = pk2(-cy, -cy), ncz = pk2(-cz, -cz);
        #pragma unroll
        for (int j = 0; j < PAIRS; j++) {
            unsigned long long dx = add2(px[j], ncx);
            unsigned long long dy = add2(py[j], ncy);
            unsigned long long dz = add2(pz[j], ncz);
            unsigned long long s  = add2(add2(mul2(dx, dx), mul2(dy, dy)), mul2(dz, dz));
            float lo, hi; up2(s, lo, hi);
            md[2*j]   = fminf(md[2*j],   lo);
            md[2*j+1] = fminf(md[2*j+1], hi);
        }

        // ---- thread-local argmax: tournament, strict > keeps the smaller index ----
        float v[PPT]; int id[PPT];
        #pragma unroll
        for (int i = 0; i < PPT; i++) { v[i] = md[i]; id[i] = i; }
        #pragma unroll
        for (int s = 1; s < PPT; s <<= 1) {
            #pragma unroll
            for (int i = 0; i < PPT; i += 2 * s)
                if (v[i + s] > v[i]) { v[i] = v[i + s]; id[i] = id[i + s]; }
        }
        const unsigned gidx = g0 + (unsigned)id[0];
        const unsigned db   = __float_as_uint(v[0]);   // dist >= 0 -> uint order == float order

        // ---- warp argmax: redux + ballot; lowest tied lane == smallest index ----
        unsigned wmax = __reduce_max_sync(0xFFFFFFFFu, db);
        unsigned ball = __ballot_sync(0xFFFFFFFFu, db == wmax);
        int srcl = __ffs(ball) - 1;
        unsigned wi = __shfl_sync(0xFFFFFFFFu, gidx, srcl);
        if (lane == 0)
            wkey[warp] = ((unsigned long long)wmax << 32)
                       | (unsigned long long)(0xFFFFFFFFu - wi);

        const int p = k & 1;
        const unsigned mbp  = p ? mb1 : mb0;
        const unsigned mbn  = p ? mb0 : mb1;

        if (warp == 0) {
            asm volatile("bar.sync 1, %0;" :: "r"(NTHREADS) : "memory");
            // ---- CTA argmax across 16 warp keys ----
            unsigned long long k64 = (lane < NWARPS) ? wkey[lane] : 0ULL;
            unsigned hi32 = (unsigned)(k64 >> 32);
            unsigned m  = __reduce_max_sync(0xFFFFFFFFu, hi32);
            unsigned bl = __ballot_sync(0xFFFFFFFFu, hi32 == m);
            int s2 = __ffs(bl) - 1;                       // lowest warp == smallest index
            unsigned long long ck = __shfl_sync(0xFFFFFFFFu, k64, s2);
            // arm NEXT phase before any push of this phase can chain to a future push
            if (lane == 8)
                asm volatile("mbarrier.arrive.expect_tx.shared::cta.b64 _, [%0], %1;"
                             :: "r"(mbn), "r"(SLOT_TX) : "memory");
            __syncwarp();
            // ---- lanes 0..7: push {key, coords} slot to cluster rank == lane ----
            if (lane < CS) {
                unsigned gi = 0xFFFFFFFFu - (unsigned)(ck & 0xFFFFFFFFull);
                unsigned li = gi - rank * NPC;            // CTA winner is always local
                float sx = xs[li], sy = ys[li], sz = zs[li];
                unsigned lslot = slots0 + (unsigned)(p * CS + rank) * 24u;
                unsigned rslot, rmbar;
                asm("mapa.shared::cluster.u32 %0, %1, %2;" : "=r"(rslot) : "r"(lslot), "r"(lane));
                asm("mapa.shared::cluster.u32 %0, %1, %2;" : "=r"(rmbar) : "r"(mbp),   "r"(lane));
                asm volatile("st.async.shared::cluster.mbarrier::complete_tx::bytes.b64 [%0], %1, [%2];"
                             :: "r"(rslot),      "l"(ck),          "r"(rmbar) : "memory");
                asm volatile("st.async.shared::cluster.mbarrier::complete_tx::bytes.b64 [%0], %1, [%2];"
                             :: "r"(rslot + 8),  "l"(pk2(sx, sy)), "r"(rmbar) : "memory");
                asm volatile("st.async.shared::cluster.mbarrier::complete_tx::bytes.b32 [%0], %1, [%2];"
                             :: "r"(rslot + 16), "f"(sz),          "r"(rmbar) : "memory");
            }
        } else {
            asm volatile("bar.arrive 1, %0;" :: "r"(NTHREADS) : "memory");
        }

        // ---- wait for all 8 slots (160 tx bytes), HW sleep ----
        unsigned phv = p ? ph1 : ph0;
        mbar_wait(mbp, phv);
        if (p) ph1 ^= 1; else ph0 ^= 1;

        // ---- every thread resolves the cluster winner (tournament over 8 slots) ----
        unsigned long long kk[CS]; int sid[CS];
        #pragma unroll
        for (int r = 0; r < CS; r++) { kk[r] = cslots[p][r][0]; sid[r] = r; }
        #pragma unroll
        for (int s = 1; s < CS; s <<= 1) {
            #pragma unroll
            for (int r = 0; r < CS; r += 2 * s)
                if (kk[r + s] > kk[r]) { kk[r] = kk[r + s]; sid[r] = sid[r + s]; }
        }
        const int wsl = sid[0];
        up2(cslots[p][wsl][1], cx, cy);
        cz = *(const float*)&cslots[p][wsl][2];

        if (rank == 0 && tid == 0) {
            unsigned widx = 0xFFFFFFFFu - (unsigned)(kk[0] & 0xFFFFFFFFull);
            out[(size_t)b * NSAMP + k] = (float)widx;
            float* os = out + BATCH * NSAMP + ((size_t)b * NSAMP + k) * 3;
            os[0] = cx; os[1] = cy; os[2] = cz;
        }
    }
}

extern "C" void kernel_launch(void* const* d_in, const int* in_sizes, int n_in,
                              void* d_out, int out_size)
{
    const float* input = (const float*)d_in[0];
    float* out = (float*)d_out;

    // 3 * 8192 * 4 = 98304 bytes dynamic SMEM for the SoA point copy
    cudaFuncSetAttribute(fps_kernel, cudaFuncAttributeMaxDynamicSharedMemorySize, 98304);

    fps_kernel<<<BATCH * CS, NTHREADS, 98304>>>(input, out);
}

// round 5
// speedup vs baseline: 3.2072x; 1.0331x over previous
#include <cuda_runtime.h>
#include <cooperative_groups.h>
#include <cstdint>

namespace cg = cooperative_groups;

#define BATCH    8
#define NPTS     65536
#define NSAMP    1024
#define NTHREADS 512
#define NWARPS   (NTHREADS / 32)    // 16

__device__ __forceinline__ unsigned long long pk2(float lo, float hi) {
    unsigned long long r; asm("mov.b64 %0,{%1,%2};" : "=l"(r) : "f"(lo), "f"(hi)); return r;
}
__device__ __forceinline__ void up2(unsigned long long v, float& lo, float& hi) {
    asm("mov.b64 {%0,%1},%2;" : "=f"(lo), "=f"(hi) : "l"(v));
}
__device__ __forceinline__ unsigned long long add2(unsigned long long a, unsigned long long b) {
    unsigned long long r; asm("add.rn.f32x2 %0,%1,%2;" : "=l"(r) : "l"(a), "l"(b)); return r;
}
__device__ __forceinline__ unsigned long long mul2(unsigned long long a, unsigned long long b) {
    unsigned long long r; asm("mul.rn.f32x2 %0,%1,%2;" : "=l"(r) : "l"(a), "l"(b)); return r;
}
__device__ __forceinline__ unsigned smem_u32(const void* p) {
    return (unsigned)__cvta_generic_to_shared(p);
}
__device__ __forceinline__ void mbar_wait(unsigned mbar, unsigned parity) {
    asm volatile(
        "{\n\t.reg .pred P;\n\t"
        "WAIT_%=:\n\t"
        "mbarrier.try_wait.parity.acquire.cta.shared::cta.b64 P, [%0], %1, 0x989680;\n\t"
        "@P bra DONE_%=;\n\t"
        "bra WAIT_%=;\n\t"
        "DONE_%=:\n\t}"
        :: "r"(mbar), "r"(parity) : "memory");
}

extern __shared__ float dynsmem[];

template<int CS>
__global__ void __launch_bounds__(NTHREADS, 1)
fps_kernel(const float* __restrict__ input, float* __restrict__ out)
{
    constexpr int NPC     = NPTS / CS;
    constexpr int PPT     = NPC / NTHREADS;
    constexpr int PAIRS   = PPT / 2;
    constexpr unsigned SLOT_TX = CS * 20;   // per-phase tx bytes: CS slots * 20B

    cg::cluster_group cluster = cg::this_cluster();
    const unsigned rank = cluster.block_rank();
    const int b    = blockIdx.x / CS;
    const int tid  = threadIdx.x;
    const int lane = tid & 31;
    const int warp = tid >> 5;

    // SMEM SoA copy of this CTA's points (winner-coordinate lookup only)
    float* xs = dynsmem;
    float* ys = xs + NPC;
    float* zs = ys + NPC;

    __shared__ unsigned long long wkey[NWARPS];
    // slot = [key:u64][xy:u64][z:u32 in low half of u64] -> 24B stride, 20B payload
    __shared__ __align__(8) unsigned long long cslots[2][CS][3];
    __shared__ __align__(8) unsigned long long mbar[2];

    const unsigned mb0 = smem_u32(&mbar[0]);
    const unsigned mb1 = smem_u32(&mbar[1]);
    const unsigned slots0 = smem_u32(&cslots[0][0][0]);

    const float* pb = input + (size_t)b * NPTS * 3;
    const unsigned g0 = rank * NPC + (unsigned)tid * PPT;

    // ---- one-time: mbarrier init (arrive count 1 = the expect_tx arrival) ----
    if (tid == 0) {
        asm volatile("mbarrier.init.shared::cta.b64 [%0], 1;" :: "r"(mb0) : "memory");
        asm volatile("mbarrier.init.shared::cta.b64 [%0], 1;" :: "r"(mb1) : "memory");
        // phase consumed at k=1 (buffer 1) must be expected before ANY push(k=1)
        asm volatile("mbarrier.arrive.expect_tx.shared::cta.b64 _, [%0], %1;"
                     :: "r"(mb1), "r"(SLOT_TX) : "memory");
    }

    // ---- one-time load: PPT points into registers (f32x2-packed) + SMEM SoA ----
    float f[PPT * 3];
    const float4* src4 = (const float4*)(pb + (size_t)g0 * 3);
    #pragma unroll
    for (int i = 0; i < (PPT * 3) / 4; i++) {
        float4 v = src4[i];
        f[4*i] = v.x; f[4*i+1] = v.y; f[4*i+2] = v.z; f[4*i+3] = v.w;
    }
    unsigned long long px[PAIRS], py[PAIRS], pz[PAIRS];
    #pragma unroll
    for (int j = 0; j < PAIRS; j++) {
        px[j] = pk2(f[6*j+0], f[6*j+3]);
        py[j] = pk2(f[6*j+1], f[6*j+4]);
        pz[j] = pk2(f[6*j+2], f[6*j+5]);
    }
    {
        const unsigned l0 = (unsigned)tid * PPT;
        #pragma unroll
        for (int i = 0; i < PPT; i++) {
            xs[l0 + i] = f[3*i]; ys[l0 + i] = f[3*i+1]; zs[l0 + i] = f[3*i+2];
        }
    }

    float md[PPT];
    #pragma unroll
    for (int i = 0; i < PPT; i++) md[i] = 1e10f;   // BIG, matches reference

    // first selection is index 0 (PointNet++ convention)
    float cx = pb[0], cy = pb[1], cz = pb[2];
    if (rank == 0 && tid == 0) {
        out[(size_t)b * NSAMP] = 0.0f;
        float* os = out + BATCH * NSAMP + (size_t)b * NSAMP * 3;
        os[0] = cx; os[1] = cy; os[2] = cz;
    }

    // all mbarrier inits + SoA tiles visible cluster-wide before any st.async
    cluster.sync();

    unsigned ph0 = 0, ph1 = 0;   // phase parity per buffer

    for (int k = 1; k < NSAMP; k++) {
        // ---- distance update (non-contracted mul/add — matches reference rounding) ----
        const unsigned long long ncx = pk2(-cx, -cx), ncy = pk2(-cy, -cy), ncz = pk2(-cz, -cz);
        #pragma unroll
        for (int j = 0; j < PAIRS; j++) {
            unsigned long long dx = add2(px[j], ncx);
            unsigned long long dy = add2(py[j], ncy);
            unsigned long long dz = add2(pz[j], ncz);
            unsigned long long s  = add2(add2(mul2(dx, dx), mul2(dy, dy)), mul2(dz, dz));
            float lo, hi; up2(s, lo, hi);
            md[2*j]   = fminf(md[2*j],   lo);
            md[2*j+1] = fminf(md[2*j+1], hi);
        }

        // ---- thread-local argmax: tournament, strict > keeps the smaller index ----
        float v[PPT]; int id[PPT];
        #pragma unroll
        for (int i = 0; i < PPT; i++) { v[i] = md[i]; id[i] = i; }
        #pragma unroll
        for (int s = 1; s < PPT; s <<= 1) {
            #pragma unroll
            for (int i = 0; i < PPT; i += 2 * s)
                if (v[i + s] > v[i]) { v[i] = v[i + s]; id[i] = id[i + s]; }
        }
        const unsigned gidx = g0 + (unsigned)id[0];
        const unsigned db   = __float_as_uint(v[0]);   // dist >= 0 -> uint order == float order

        // ---- warp argmax: redux + ballot; lowest tied lane == smallest index ----
        unsigned wmax = __reduce_max_sync(0xFFFFFFFFu, db);
        unsigned ball = __ballot_sync(0xFFFFFFFFu, db == wmax);
        int srcl = __ffs(ball) - 1;
        unsigned wi = __shfl_sync(0xFFFFFFFFu, gidx, srcl);
        if (lane == 0)
            wkey[warp] = ((unsigned long long)wmax << 32)
                       | (unsigned long long)(0xFFFFFFFFu - wi);

        const int p = k & 1;
        const unsigned mbp = p ? mb1 : mb0;
        const unsigned mbn = p ? mb0 : mb1;

        if (warp == 0) {
            asm volatile("bar.sync 1, %0;" :: "r"(NTHREADS) : "memory");
            // ---- CTA argmax across 16 warp keys ----
            unsigned long long k64 = (lane < NWARPS) ? wkey[lane] : 0ULL;
            unsigned hi32 = (unsigned)(k64 >> 32);
            unsigned m  = __reduce_max_sync(0xFFFFFFFFu, hi32);
            unsigned bl = __ballot_sync(0xFFFFFFFFu, hi32 == m);
            int s2 = __ffs(bl) - 1;                       // lowest warp == smallest index
            unsigned long long ck = __shfl_sync(0xFFFFFFFFu, k64, s2);
            // arm NEXT phase before any push of this phase can chain to a future push
            if (lane == CS)
                asm volatile("mbarrier.arrive.expect_tx.shared::cta.b64 _, [%0], %1;"
                             :: "r"(mbn), "r"(SLOT_TX) : "memory");
            __syncwarp();
            // ---- lanes 0..CS-1: push {key, coords} slot to cluster rank == lane ----
            if (lane < CS) {
                unsigned gi = 0xFFFFFFFFu - (unsigned)(ck & 0xFFFFFFFFull);
                unsigned li = gi - rank * NPC;            // CTA winner is always local
                float sx = xs[li], sy = ys[li], sz = zs[li];
                unsigned lslot = slots0 + (unsigned)(p * CS + rank) * 24u;
                unsigned rslot, rmbar;
                asm("mapa.shared::cluster.u32 %0, %1, %2;" : "=r"(rslot) : "r"(lslot), "r"(lane));
                asm("mapa.shared::cluster.u32 %0, %1, %2;" : "=r"(rmbar) : "r"(mbp),   "r"(lane));
                asm volatile("st.async.shared::cluster.mbarrier::complete_tx::bytes.b64 [%0], %1, [%2];"
                             :: "r"(rslot),      "l"(ck),          "r"(rmbar) : "memory");
                asm volatile("st.async.shared::cluster.mbarrier::complete_tx::bytes.b64 [%0], %1, [%2];"
                             :: "r"(rslot + 8),  "l"(pk2(sx, sy)), "r"(rmbar) : "memory");
                asm volatile("st.async.shared::cluster.mbarrier::complete_tx::bytes.b32 [%0], %1, [%2];"
                             :: "r"(rslot + 16), "f"(sz),          "r"(rmbar) : "memory");
            }
        } else {
            asm volatile("bar.arrive 1, %0;" :: "r"(NTHREADS) : "memory");
        }

        // ---- wait for all CS slots (SLOT_TX bytes), HW sleep ----
        unsigned phv = p ? ph1 : ph0;
        mbar_wait(mbp, phv);
        if (p) ph1 ^= 1; else ph0 ^= 1;

        // ---- cluster winner via warp redux (lanes 0..CS-1 each own one slot) ----
        unsigned long long myk = (lane < CS) ? cslots[p][lane][0] : 0ULL;
        unsigned khi = (unsigned)(myk >> 32);
        unsigned m1  = __reduce_max_sync(0xFFFFFFFFu, khi);
        unsigned klo = (khi == m1) ? (unsigned)myk : 0u;    // lo32 = ~idx > 0 for real slots
        unsigned m2  = __reduce_max_sync(0xFFFFFFFFu, klo); // max ~idx == min index
        unsigned bw  = __ballot_sync(0xFFFFFFFFu, (khi == m1) & (klo == m2));
        const int ws = __ffs(bw) - 1;                       // winning slot index
        up2(cslots[p][ws][1], cx, cy);                      // broadcast LDS
        cz = *(const float*)&cslots[p][ws][2];

        if (rank == 0 && tid == 0) {
            out[(size_t)b * NSAMP + k] = (float)(0xFFFFFFFFu - m2);
            float* os = out + BATCH * NSAMP + ((size_t)b * NSAMP + k) * 3;
            os[0] = cx; os[1] = cy; os[2] = cz;
        }
    }
}

extern "C" void kernel_launch(void* const* d_in, const int* in_sizes, int n_in,
                              void* d_out, int out_size)
{
    const float* input = (const float*)d_in[0];
    float* out = (float*)d_out;

    const int smem16 = 3 * (NPTS / 16) * 4;   // 48 KB
    const int smem8  = 3 * (NPTS / 8)  * 4;   // 96 KB

    cudaFuncSetAttribute(fps_kernel<16>, cudaFuncAttributeNonPortableClusterSizeAllowed, 1);
    cudaFuncSetAttribute(fps_kernel<16>, cudaFuncAttributeMaxDynamicSharedMemorySize, smem16);
    cudaFuncSetAttribute(fps_kernel<8>,  cudaFuncAttributeMaxDynamicSharedMemorySize, smem8);

    cudaLaunchConfig_t cfg = {};
    cfg.blockDim = {NTHREADS, 1, 1};
    cfg.stream = 0;
    cudaLaunchAttribute attr[1];
    attr[0].id = cudaLaunchAttributeClusterDimension;

    attr[0].val.clusterDim = {16, 1, 1};
    cfg.attrs = attr; cfg.numAttrs = 1;
    cfg.gridDim = {BATCH * 16, 1, 1};
    cfg.dynamicSmemBytes = smem16;

    int maxCluster = 0;
    cudaOccupancyMaxPotentialClusterSize(&maxCluster, fps_kernel<16>, &cfg);

    if (maxCluster >= 16) {
        cudaLaunchKernelEx(&cfg, fps_kernel<16>, input, out);
    } else {
        attr[0].val.clusterDim = {8, 1, 1};
        cfg.gridDim = {BATCH * 8, 1, 1};
        cfg.dynamicSmemBytes = smem8;
        cudaLaunchKernelEx(&cfg, fps_kernel<8>, input, out);
    }
}